// round 5
// baseline (speedup 1.0000x reference)
#include <cuda_runtime.h>
#include <cuda_bf16.h>

// Problem constants (fixed by setup_inputs): length=8192, n=4096.
#define ENC_LEN   8192
#define ENC_VEC4  (ENC_LEN / 4)   // 2048 float4 per row
#define BLOCK     512

// Rows [0, RESIDENT_ROWS) are pinned in L2 (evict_last): rewritten in place
// every graph replay, never drained to DRAM in steady state.
// Rows [RESIDENT_ROWS, n) are streamed (evict_first) to DRAM.
// 3456 rows * 32 KB = 108 MB vs ~126 MB L2 (~86%, margin for hash imbalance).
#define RESIDENT_ROWS 3456

// inv_freq(base) = 1000^(-base/8192) = exp2(-(base/8192) * log2(1000))
__device__ __forceinline__ float inv_freq(int base) {
    const double Ld = 9.965784284662087;          // log2(1000)
    const float  Lh = (float)Ld;
    const float  Ll = (float)(Ld - (double)Lh);   // low-order correction
    float e   = (float)base * (1.0f / 8192.0f);   // exact (base < 2^13)
    float p   = e * Lh;
    float err = fmaf(e, Lh, -p);                  // exact residual of e*Lh
    float t   = p + fmaf(e, Ll, err);             // ≈ e * log2(1000)
    return exp2f(-t);
}

__device__ __forceinline__ unsigned long long pack2(float x, float y) {
    unsigned long long r;
    asm("mov.b64 %0, {%1, %2};" : "=l"(r) : "f"(x), "f"(y));
    return r;
}

// 32-byte pinned store (sm_103 requires .v4.b64 width for evict_last).
__device__ __forceinline__ void st_resident32B(void* p, const unsigned long long* q) {
    asm volatile("st.global.L2::evict_last.v4.b64 [%0], {%1, %2, %3, %4};"
                 :: "l"(p), "l"(q[0]), "l"(q[1]), "l"(q[2]), "l"(q[3])
                 : "memory");
}

// 32-byte streaming store (evict-first; overflow portion drains to DRAM
// without displacing the resident set).
__device__ __forceinline__ void st_stream32B(void* p, const unsigned long long* q) {
    asm volatile("st.global.cs.v4.b64 [%0], {%1, %2, %3, %4};"
                 :: "l"(p), "l"(q[0]), "l"(q[1]), "l"(q[2]), "l"(q[3])
                 : "memory");
}

// ---------------------------------------------------------------------------
// Fused kernel. Each thread owns two contiguous 32B chunks of the row:
//   chunk A: elements [8t, 8t+8)            (float4 indices 2t, 2t+1)
//   chunk B: elements [8t+4096, 8t+4104)    (float4 indices 2t+1024, 2t+1025)
// computed once into registers, then broadcast to all n rows with 32B stores.
// ---------------------------------------------------------------------------
__global__ void __launch_bounds__(BLOCK)
sinusoidal_fused_kernel(const float* __restrict__ position,
                        float* __restrict__ out, int n) {
    const int tid = threadIdx.x;
    const float pos = position[0];

    // Two 32B chunks = 16 floats = 8 (sin,cos) pairs.
    unsigned long long qa[4], qb[4];
#pragma unroll
    for (int k = 0; k < 4; ++k) {
        // chunk A pair k covers elements 8*tid + 2k, 8*tid + 2k + 1
        int baseA = 8 * tid + 2 * k;
        float aA = pos * inv_freq(baseA);
        float sA, cA;
        sincosf(aA, &sA, &cA);
        qa[k] = pack2(sA, cA);

        int baseB = baseA + 4096;
        float aB = pos * inv_freq(baseB);
        float sB, cB;
        sincosf(aB, &sB, &cB);
        qb[k] = pack2(sB, cB);
    }

    const int offA = 8 * tid;          // float offset of chunk A
    const int offB = 8 * tid + 4096;   // float offset of chunk B

    for (int row = blockIdx.x; row < n; row += gridDim.x) {
        float* __restrict__ dst = out + (size_t)row * ENC_LEN;
        if (row < RESIDENT_ROWS) {
            st_resident32B(dst + offA, qa);
            st_resident32B(dst + offB, qb);
        } else {
            st_stream32B(dst + offA, qa);
            st_stream32B(dst + offB, qb);
        }
    }
}

extern "C" void kernel_launch(void* const* d_in, const int* in_sizes, int n_in,
                              void* d_out, int out_size) {
    // setup_inputs order: length (scalar), n (scalar), position (float[1]).
    const float* position = (const float*)d_in[n_in - 1];

    const int n = out_size / ENC_LEN;     // 4096

    // 4 CTAs/SM (148 SMs) -> 592 CTAs; each writes ~7 rows.
    int grid = 592;
    if (grid > n) grid = n;
    sinusoidal_fused_kernel<<<grid, BLOCK>>>(position, (float*)d_out, n);
}

// round 6
// speedup vs baseline: 1.0083x; 1.0083x over previous
#include <cuda_runtime.h>
#include <cuda_bf16.h>

// Problem constants (fixed by setup_inputs): length=8192, n=4096.
#define ENC_LEN   8192
#define BLOCK     512

// Rows [0, RESIDENT_ROWS) pinned in L2 (evict_last): rewritten in place every
// graph replay -> no DRAM drain for them in steady state.
// 2048 rows * 32 KB = 64 MB ~= 51% of the ~126 MB L2: every hash set keeps
// slack so the streamed portion (.cs) flows through without displacing
// residents (the 86%-resident attempt in R5 overflowed sets and regressed).
#define RESIDENT_ROWS 2048

// inv_freq(base) = 1000^(-base/8192) = exp2(-(base/8192) * log2(1000))
__device__ __forceinline__ float inv_freq(int base) {
    const double Ld = 9.965784284662087;          // log2(1000)
    const float  Lh = (float)Ld;
    const float  Ll = (float)(Ld - (double)Lh);   // low-order correction
    float e   = (float)base * (1.0f / 8192.0f);   // exact (base < 2^13)
    float p   = e * Lh;
    float err = fmaf(e, Lh, -p);                  // exact residual of e*Lh
    float t   = p + fmaf(e, Ll, err);             // ≈ e * log2(1000)
    return exp2f(-t);
}

__device__ __forceinline__ unsigned long long pack2(float x, float y) {
    unsigned long long r;
    asm("mov.b64 %0, {%1, %2};" : "=l"(r) : "f"(x), "f"(y));
    return r;
}

// 32-byte pinned store (sm_103 requires .v4.b64 width for evict_last).
__device__ __forceinline__ void st_resident32B(void* p, const unsigned long long* q) {
    asm volatile("st.global.L2::evict_last.v4.b64 [%0], {%1, %2, %3, %4};"
                 :: "l"(p), "l"(q[0]), "l"(q[1]), "l"(q[2]), "l"(q[3])
                 : "memory");
}

// 32-byte streaming store (evict-first).
__device__ __forceinline__ void st_stream32B(void* p, const unsigned long long* q) {
    asm volatile("st.global.cs.v4.b64 [%0], {%1, %2, %3, %4};"
                 :: "l"(p), "l"(q[0]), "l"(q[1]), "l"(q[2]), "l"(q[3])
                 : "memory");
}

// ---------------------------------------------------------------------------
// Fused kernel. Each thread owns two contiguous 32B chunks of the row:
//   chunk A: elements [8t, 8t+8)
//   chunk B: elements [8t+4096, 8t+4104)
// computed once into registers, then broadcast to all n rows with 32B stores.
// ---------------------------------------------------------------------------
__global__ void __launch_bounds__(BLOCK)
sinusoidal_fused_kernel(const float* __restrict__ position,
                        float* __restrict__ out, int n) {
    const int tid = threadIdx.x;
    const float pos = position[0];

    unsigned long long qa[4], qb[4];
#pragma unroll
    for (int k = 0; k < 4; ++k) {
        int baseA = 8 * tid + 2 * k;
        float aA = pos * inv_freq(baseA);
        float sA, cA;
        sincosf(aA, &sA, &cA);
        qa[k] = pack2(sA, cA);

        int baseB = baseA + 4096;
        float aB = pos * inv_freq(baseB);
        float sB, cB;
        sincosf(aB, &sB, &cB);
        qb[k] = pack2(sB, cB);
    }

    const int offA = 8 * tid;
    const int offB = 8 * tid + 4096;

    for (int row = blockIdx.x; row < n; row += gridDim.x) {
        float* __restrict__ dst = out + (size_t)row * ENC_LEN;
        if (row < RESIDENT_ROWS) {
            st_resident32B(dst + offA, qa);
            st_resident32B(dst + offB, qb);
        } else {
            st_stream32B(dst + offA, qa);
            st_stream32B(dst + offB, qb);
        }
    }
}

extern "C" void kernel_launch(void* const* d_in, const int* in_sizes, int n_in,
                              void* d_out, int out_size) {
    // setup_inputs order: length (scalar), n (scalar), position (float[1]).
    const float* position = (const float*)d_in[n_in - 1];

    const int n = out_size / ENC_LEN;     // 4096

    int grid = 592;                        // 4 CTAs/SM * 148 SMs
    if (grid > n) grid = n;
    sinusoidal_fused_kernel<<<grid, BLOCK>>>(position, (float*)d_out, n);
}

// round 7
// speedup vs baseline: 1.0376x; 1.0291x over previous
#include <cuda_runtime.h>
#include <cuda_bf16.h>

// Problem constants (fixed by setup_inputs): length=8192, n=4096.
#define ENC_LEN   8192
#define BLOCK     512

// inv_freq(base) = 1000^(-base/8192) = exp2(-(base/8192) * log2(1000))
// Compensated fp32 product keeps the exp2 argument accurate to ~1 ulp.
__device__ __forceinline__ float inv_freq(int base) {
    const double Ld = 9.965784284662087;          // log2(1000)
    const float  Lh = (float)Ld;
    const float  Ll = (float)(Ld - (double)Lh);   // low-order correction
    float e   = (float)base * (1.0f / 8192.0f);   // exact (base < 2^13)
    float p   = e * Lh;
    float err = fmaf(e, Lh, -p);                  // exact residual of e*Lh
    float t   = p + fmaf(e, Ll, err);             // ≈ e * log2(1000)
    return exp2f(-t);
}

__device__ __forceinline__ unsigned long long pack2(float x, float y) {
    unsigned long long r;
    asm("mov.b64 %0, {%1, %2};" : "=l"(r) : "f"(x), "f"(y));
    return r;
}

// Plain 32-byte store, default L2 policy (hints measurably cost throughput
// here: every .cs / evict_last variant ran 0.3-0.9us slower than default).
__device__ __forceinline__ void st32B(void* p, const unsigned long long* q) {
    asm volatile("st.global.v4.b64 [%0], {%1, %2, %3, %4};"
                 :: "l"(p), "l"(q[0]), "l"(q[1]), "l"(q[2]), "l"(q[3])
                 : "memory");
}

// ---------------------------------------------------------------------------
// Fused kernel. Each thread owns two contiguous 32B chunks of the row:
//   chunk A: elements [8t, 8t+8)
//   chunk B: elements [8t+4096, 8t+4104)
// computed once into registers, then broadcast to all n rows. 2-row unroll
// keeps 4 independent 256-bit stores in flight per warp per iteration.
// Runtime is LTS(write)-bound: 134MB @ ~6.1TB/s.
// ---------------------------------------------------------------------------
__global__ void __launch_bounds__(BLOCK)
sinusoidal_fused_kernel(const float* __restrict__ position,
                        float* __restrict__ out, int n) {
    const int tid = threadIdx.x;
    const float pos = position[0];

    unsigned long long qa[4], qb[4];
#pragma unroll
    for (int k = 0; k < 4; ++k) {
        int baseA = 8 * tid + 2 * k;
        float aA = pos * inv_freq(baseA);
        float sA, cA;
        sincosf(aA, &sA, &cA);
        qa[k] = pack2(sA, cA);

        int baseB = baseA + 4096;
        float aB = pos * inv_freq(baseB);
        float sB, cB;
        sincosf(aB, &sB, &cB);
        qb[k] = pack2(sB, cB);
    }

    const int offA = 8 * tid;
    const int offB = 8 * tid + 4096;

    // 2-row unrolled broadcast loop: 4 independent 32B stores per iteration.
    int row = blockIdx.x * 2;
    const int stride = gridDim.x * 2;
    for (; row + 1 < n; row += stride) {
        float* __restrict__ d0 = out + (size_t)row * ENC_LEN;
        float* __restrict__ d1 = d0 + ENC_LEN;
        st32B(d0 + offA, qa);
        st32B(d0 + offB, qb);
        st32B(d1 + offA, qa);
        st32B(d1 + offB, qb);
    }
    if (row < n) {
        float* __restrict__ d0 = out + (size_t)row * ENC_LEN;
        st32B(d0 + offA, qa);
        st32B(d0 + offB, qb);
    }
}

extern "C" void kernel_launch(void* const* d_in, const int* in_sizes, int n_in,
                              void* d_out, int out_size) {
    // setup_inputs order: length (scalar), n (scalar), position (float[1]).
    const float* position = (const float*)d_in[n_in - 1];

    const int n = out_size / ENC_LEN;     // 4096

    // 2 CTAs/SM (148 SMs) -> 296 CTAs: measurably faster than 592 here
    // (less cross-CTA L1tex queue contention).
    int grid = 296;
    if (grid * 2 > n) grid = (n + 1) / 2;
    sinusoidal_fused_kernel<<<grid, BLOCK>>>(position, (float*)d_out, n);
}

// round 8
// speedup vs baseline: 1.0906x; 1.0510x over previous
#include <cuda_runtime.h>
#include <cuda_bf16.h>

// Problem constants (fixed by setup_inputs): length=8192, n=4096.
#define ENC_LEN   8192
#define BLOCK     512

// inv_freq(base) = 1000^(-base/8192) = exp2(-(base/8192) * log2(1000))
// Compensated fp32 product keeps the exp2 argument accurate to ~1 ulp.
__device__ __forceinline__ float inv_freq(int base) {
    const double Ld = 9.965784284662087;          // log2(1000)
    const float  Lh = (float)Ld;
    const float  Ll = (float)(Ld - (double)Lh);   // low-order correction
    float e   = (float)base * (1.0f / 8192.0f);   // exact (base < 2^13)
    float p   = e * Lh;
    float err = fmaf(e, Lh, -p);                  // exact residual of e*Lh
    float t   = p + fmaf(e, Ll, err);             // ≈ e * log2(1000)
    return exp2f(-t);
}

__device__ __forceinline__ unsigned long long pack2(float x, float y) {
    unsigned long long r;
    asm("mov.b64 %0, {%1, %2};" : "=l"(r) : "f"(x), "f"(y));
    return r;
}

// Plain 32-byte store, default L2 policy. Measured across rounds: cache
// hints (.cs, evict_last) never improved the steady-state period — it is
// pinned by the mandatory 134MB/replay DRAM write drain (~5.1TB/s).
__device__ __forceinline__ void st32B(void* p, const unsigned long long* q) {
    asm volatile("st.global.v4.b64 [%0], {%1, %2, %3, %4};"
                 :: "l"(p), "l"(q[0]), "l"(q[1]), "l"(q[2]), "l"(q[3])
                 : "memory");
}

// ---------------------------------------------------------------------------
// Fused kernel. Each thread owns two contiguous 32B chunks of the row:
//   chunk A: elements [8t, 8t+8)
//   chunk B: elements [8t+4096, 8t+4104)
// computed once into registers (8 sincosf + 8 exp2f), then broadcast to all
// n rows with 256-bit stores, 2 rows per iteration (4 independent stores in
// flight per warp). Runtime: HBM-write-bound at the chip floor.
// ---------------------------------------------------------------------------
__global__ void __launch_bounds__(BLOCK)
sinusoidal_fused_kernel(const float* __restrict__ position,
                        float* __restrict__ out, int n) {
    const int tid = threadIdx.x;
    const float pos = position[0];

    unsigned long long qa[4], qb[4];
#pragma unroll
    for (int k = 0; k < 4; ++k) {
        int baseA = 8 * tid + 2 * k;
        float aA = pos * inv_freq(baseA);
        float sA, cA;
        sincosf(aA, &sA, &cA);
        qa[k] = pack2(sA, cA);

        int baseB = baseA + 4096;
        float aB = pos * inv_freq(baseB);
        float sB, cB;
        sincosf(aB, &sB, &cB);
        qb[k] = pack2(sB, cB);
    }

    const int offA = 8 * tid;
    const int offB = 8 * tid + 4096;

    // 2-row unrolled broadcast loop.
    int row = blockIdx.x * 2;
    const int stride = gridDim.x * 2;
    for (; row + 1 < n; row += stride) {
        float* __restrict__ d0 = out + (size_t)row * ENC_LEN;
        float* __restrict__ d1 = d0 + ENC_LEN;
        st32B(d0 + offA, qa);
        st32B(d0 + offB, qb);
        st32B(d1 + offA, qa);
        st32B(d1 + offB, qb);
    }
    if (row < n) {
        float* __restrict__ d0 = out + (size_t)row * ENC_LEN;
        st32B(d0 + offA, qa);
        st32B(d0 + offB, qb);
    }
}

extern "C" void kernel_launch(void* const* d_in, const int* in_sizes, int n_in,
                              void* d_out, int out_size) {
    // setup_inputs order: length (scalar), n (scalar), position (float[1]).
    const float* position = (const float*)d_in[n_in - 1];

    const int n = out_size / ENC_LEN;     // 4096

    // 4 CTAs/SM (148 SMs) -> 592 CTAs, the best-measured grid (R3).
    int grid = 592;
    if (grid * 2 > n) grid = (n + 1) / 2;
    sinusoidal_fused_kernel<<<grid, BLOCK>>>(position, (float*)d_out, n);
}